// round 3
// baseline (speedup 1.0000x reference)
#include <cuda_runtime.h>
#include <cuda_bf16.h>
#include <mma.h>
#include <cstdint>

using namespace nvcuda;

// ESSAttn: b=8, C=64, H=W=256, N=65536
// Layouts: x, scratch (q2n,k2d,v), out are [b][C][N]  (b<<22 | c<<16 | n)

#define NPIX 65536
#define CHN  64
#define NBAT 8

// ---------------- scratch (device globals; allocation-free) ----------------
__device__ float g_q2n[(size_t)NBAT * CHN * NPIX];
__device__ float g_k2d[(size_t)NBAT * CHN * NPIX];
__device__ float g_v  [(size_t)NBAT * CHN * NPIX];
__device__ float g_M  [NBAT * CHN * CHN];
__device__ float g_css[NBAT * CHN];
// weights pre-split to bf16 hi/lo; row-major [out_ch][in_ch] == col-major matrix_b (ld=64)
__device__ __nv_bfloat16 g_wqhi[192 * 64], g_wqlo[192 * 64];
__device__ __nv_bfloat16 g_wlhi[64 * 64],  g_wllo[64 * 64];
__device__ __nv_bfloat16 g_kvThi[NBAT * 64 * 64], g_kvTlo[NBAT * 64 * 64];

// ---------------------------------------------------------------------------
// prep: split weights to bf16 hi/lo, zero accumulators
__global__ void essa_prep(const float* __restrict__ wqkv, const float* __restrict__ wln) {
    int i = blockIdx.x * 256 + threadIdx.x;   // grid 128 -> 32768
    if (i < 12288) {
        float v = wqkv[i];
        __nv_bfloat16 h = __float2bfloat16(v);
        g_wqhi[i] = h;
        g_wqlo[i] = __float2bfloat16(v - __bfloat162float(h));
    }
    if (i < 4096) {
        float v = wln[i];
        __nv_bfloat16 h = __float2bfloat16(v);
        g_wlhi[i] = h;
        g_wllo[i] = __float2bfloat16(v - __bfloat162float(h));
    }
    if (i < NBAT * CHN * CHN) g_M[i] = 0.f;
    if (i < NBAT * CHN)       g_css[i] = 0.f;
}

// ---------------------------------------------------------------------------
// qkv via wmma bf16 split: per CTA 64 pixels, D[64,192] = x_tile @ Wqkv^T.
// D = Ah*Bh + Ah*Bl + Al*Bh. A stored col-major [k][m] in smem (ld=64).
// Result C stored col-major [n][m] (ld=64) -> conflict-free per-pixel epilogue.
__global__ __launch_bounds__(128) void essa_qkv_tc(const float* __restrict__ x,
                                                   const float* __restrict__ bqkv) {
    __shared__ __align__(128) char sm[49152];          // C (48KB) overlaps Ah|Al (16KB)
    __nv_bfloat16* Ah = reinterpret_cast<__nv_bfloat16*>(sm);
    __nv_bfloat16* Al = Ah + 4096;
    float* C = reinterpret_cast<float*>(sm);

    const int tid = threadIdx.x;
    const int wid = tid >> 5;
    const int b = blockIdx.y;
    const int n0 = blockIdx.x << 6;
    const size_t base = (size_t)b << 22;

    // ---- load x tile, split to bf16 hi/lo, store A col-major ----
    {
        const int p = tid & 63, kh = (tid >> 6) << 5;
        const int n = n0 + p;
        for (int i = 0; i < 32; ++i) {
            int k = kh + i;
            float v = x[base + ((size_t)k << 16) + n];
            __nv_bfloat16 h = __float2bfloat16(v);
            Ah[k * 64 + p] = h;
            Al[k * 64 + p] = __float2bfloat16(v - __bfloat162float(h));
        }
    }
    __syncthreads();

    // ---- MMA: warp w covers N-tiles 3w..3w+2 (16 cols each), M-tiles 0..3 ----
    wmma::fragment<wmma::accumulator, 16, 16, 16, float> acc[4][3];
#pragma unroll
    for (int mt = 0; mt < 4; ++mt)
#pragma unroll
        for (int j = 0; j < 3; ++j) wmma::fill_fragment(acc[mt][j], 0.f);

    const int nt0 = wid * 3;
#pragma unroll
    for (int term = 0; term < 3; ++term) {
        const __nv_bfloat16* Ap = (term == 2) ? Al : Ah;
        const __nv_bfloat16* Bp = (term == 1) ? g_wqlo : g_wqhi;
#pragma unroll
        for (int ks = 0; ks < 4; ++ks) {
            wmma::fragment<wmma::matrix_b, 16, 16, 16, __nv_bfloat16, wmma::col_major> bf[3];
#pragma unroll
            for (int j = 0; j < 3; ++j)
                wmma::load_matrix_sync(bf[j], Bp + (nt0 + j) * 16 * 64 + ks * 16, 64);
#pragma unroll
            for (int mt = 0; mt < 4; ++mt) {
                wmma::fragment<wmma::matrix_a, 16, 16, 16, __nv_bfloat16, wmma::col_major> af;
                wmma::load_matrix_sync(af, Ap + ks * 16 * 64 + mt * 16, 64);
#pragma unroll
                for (int j = 0; j < 3; ++j)
                    wmma::mma_sync(acc[mt][j], af, bf[j], acc[mt][j]);
            }
        }
    }
    __syncthreads();   // all A reads done; reuse region for C
#pragma unroll
    for (int mt = 0; mt < 4; ++mt)
#pragma unroll
        for (int j = 0; j < 3; ++j)
            wmma::store_matrix_sync(C + (nt0 + j) * 16 * 64 + mt * 16, acc[mt][j],
                                    64, wmma::mem_col_major);
    __syncthreads();

    // ---- epilogues (C col-major: C[ch*64 + pixel], conflict-free) ----
    if (tid < 64) {
        // Q stats: pixel = tid
        const int p = tid, n = n0 + p;
        float qv[64];
#pragma unroll 8
        for (int j = 0; j < 64; ++j) qv[j] = C[j * 64 + p] + bqkv[j];
        float mean = 0.f;
#pragma unroll 8
        for (int j = 0; j < 64; ++j) mean += qv[j];
        mean *= (1.f / 64.f);
        float ss = 0.f;
#pragma unroll 8
        for (int j = 0; j < 64; ++j) { float t = qv[j] - mean; t = t * t; qv[j] = t; ss += t; }
        float inv = 1.f / (ss + 1e-7f);
        float nr = 0.f;
#pragma unroll 8
        for (int j = 0; j < 64; ++j) { float t = qv[j] * inv; nr = fmaf(t, t, nr); }
        float sc = inv / fmaxf(sqrtf(nr), 1e-12f);
#pragma unroll 8
        for (int j = 0; j < 64; ++j) g_q2n[base + ((size_t)j << 16) + n] = qv[j] * sc;
    } else {
        // K stats: pixel = tid - 64
        const int p = tid - 64, n = n0 + p;
        float kv[64];
#pragma unroll 8
        for (int j = 0; j < 64; ++j) kv[j] = C[(64 + j) * 64 + p] + bqkv[64 + j];
        float mean = 0.f;
#pragma unroll 8
        for (int j = 0; j < 64; ++j) mean += kv[j];
        mean *= (1.f / 64.f);
        float ss = 0.f;
#pragma unroll 8
        for (int j = 0; j < 64; ++j) { float t = kv[j] - mean; t = t * t; kv[j] = t; ss += t; }
        float inv = 1.f / (ss + 1e-7f);
#pragma unroll 8
        for (int j = 0; j < 64; ++j) g_k2d[base + ((size_t)j << 16) + n] = kv[j] * inv;
    }
    // V: all threads; pixel = tid&63, channel half = (tid>>6)*32
    {
        const int p = tid & 63, jh = (tid >> 6) << 5;
        const int n = n0 + p;
#pragma unroll 8
        for (int i = 0; i < 32; ++i) {
            int j = jh + i;
            g_v[base + ((size_t)j << 16) + n] = C[(128 + j) * 64 + p] + bqkv[128 + j];
        }
    }
}

// ---------------------------------------------------------------------------
// Kernel M: M[c][d] += sum_n k2d[n][c]*v[n][d], plus column sumsq of k2d (fp32)
__global__ __launch_bounds__(256) void essa_kvacc() {
    const int b = blockIdx.y;
    const int n0 = blockIdx.x << 9;
    const size_t base = (size_t)b << 22;

    __shared__ float ks[64 * 33];
    __shared__ float vs[64 * 33];

    const int ty = threadIdx.x >> 4;
    const int tx = threadIdx.x & 15;

    float acc[4][4];
#pragma unroll
    for (int i = 0; i < 4; ++i)
#pragma unroll
        for (int j = 0; j < 4; ++j) acc[i][j] = 0.f;
    float cssr = 0.f;

    for (int t = 0; t < 16; ++t) {
        const int nb = n0 + (t << 5);
        __syncthreads();
        for (int i = threadIdx.x; i < 2048; i += 256) {
            int c = i >> 5, nn = i & 31;
            size_t g = base + ((size_t)c << 16) + nb + nn;
            ks[c * 33 + nn] = g_k2d[g];
            vs[c * 33 + nn] = g_v[g];
        }
        __syncthreads();
        const float* kp = ks + (ty << 2) * 33;
        const float* vp = vs + (tx << 2) * 33;
#pragma unroll 8
        for (int nn = 0; nn < 32; ++nn) {
            float k0 = kp[nn], k1 = kp[33 + nn], k2 = kp[66 + nn], k3 = kp[99 + nn];
            float v0 = vp[nn], v1 = vp[33 + nn], v2 = vp[66 + nn], v3 = vp[99 + nn];
            acc[0][0] = fmaf(k0, v0, acc[0][0]); acc[0][1] = fmaf(k0, v1, acc[0][1]);
            acc[0][2] = fmaf(k0, v2, acc[0][2]); acc[0][3] = fmaf(k0, v3, acc[0][3]);
            acc[1][0] = fmaf(k1, v0, acc[1][0]); acc[1][1] = fmaf(k1, v1, acc[1][1]);
            acc[1][2] = fmaf(k1, v2, acc[1][2]); acc[1][3] = fmaf(k1, v3, acc[1][3]);
            acc[2][0] = fmaf(k2, v0, acc[2][0]); acc[2][1] = fmaf(k2, v1, acc[2][1]);
            acc[2][2] = fmaf(k2, v2, acc[2][2]); acc[2][3] = fmaf(k2, v3, acc[2][3]);
            acc[3][0] = fmaf(k3, v0, acc[3][0]); acc[3][1] = fmaf(k3, v1, acc[3][1]);
            acc[3][2] = fmaf(k3, v2, acc[3][2]); acc[3][3] = fmaf(k3, v3, acc[3][3]);
        }
        if (threadIdx.x < 64) {
            const float* cp = ks + threadIdx.x * 33;
#pragma unroll 8
            for (int nn = 0; nn < 32; ++nn) { float u = cp[nn]; cssr = fmaf(u, u, cssr); }
        }
    }

    float* Mp = g_M + (b << 12);
#pragma unroll
    for (int i = 0; i < 4; ++i)
#pragma unroll
        for (int j = 0; j < 4; ++j)
            atomicAdd(&Mp[((ty << 2) + i) * 64 + (tx << 2) + j], acc[i][j]);
    if (threadIdx.x < 64) atomicAdd(&g_css[(b << 6) + threadIdx.x], cssr);
}

// ---------------------------------------------------------------------------
// kv[c][d] = M[c][d] / max(||k2d[:,c]||, 1e-12) -> transposed, split-bf16
__global__ void essa_kvfin() {
    int i = blockIdx.x * 256 + threadIdx.x;   // grid 128 -> 32768
    int b = i >> 12;
    int r = i & 4095;
    int c = r >> 6, d = r & 63;
    float nrm = fmaxf(sqrtf(g_css[(b << 6) + c]), 1e-12f);
    float v = g_M[i] / nrm;
    __nv_bfloat16 h = __float2bfloat16(v);
    int o = (b << 12) + (d << 6) + c;
    g_kvThi[o] = h;
    g_kvTlo[o] = __float2bfloat16(v - __bfloat162float(h));
}

// ---------------------------------------------------------------------------
// out via wmma: MMA1 t2 = q2n @ kvT^T (scaled 1/256), attn = v + t2,
// MMA2 out = attn @ wln^T + bln. Per CTA 64 pixels, 128 threads.
__global__ __launch_bounds__(128) void essa_out_tc(const float* __restrict__ bln,
                                                   float* __restrict__ out) {
    __shared__ __align__(128) __nv_bfloat16 Ah[4096];   // [k][m] col-major ld=64
    __shared__ __align__(128) __nv_bfloat16 Al[4096];
    __shared__ __align__(128) float C[4096];            // [n][m] col-major ld=64

    const int tid = threadIdx.x;
    const int wid = tid >> 5;
    const int b = blockIdx.y;
    const int n0 = blockIdx.x << 6;
    const size_t base = (size_t)b << 22;

    // ---- A = q2n tile (split) ----
    {
        const int p = tid & 63, kh = (tid >> 6) << 5;
        const int n = n0 + p;
        for (int i = 0; i < 32; ++i) {
            int k = kh + i;
            float v = g_q2n[base + ((size_t)k << 16) + n];
            __nv_bfloat16 h = __float2bfloat16(v);
            Ah[k * 64 + p] = h;
            Al[k * 64 + p] = __float2bfloat16(v - __bfloat162float(h));
        }
    }
    __syncthreads();

    wmma::fragment<wmma::accumulator, 16, 16, 16, float> acc[4];

    // ---- MMA1: B = kvT (per batch) ----
#pragma unroll
    for (int mt = 0; mt < 4; ++mt) wmma::fill_fragment(acc[mt], 0.f);
    {
        const __nv_bfloat16* Bhi = g_kvThi + (b << 12);
        const __nv_bfloat16* Blo = g_kvTlo + (b << 12);
#pragma unroll
        for (int term = 0; term < 3; ++term) {
            const __nv_bfloat16* Ap = (term == 2) ? Al : Ah;
            const __nv_bfloat16* Bp = (term == 1) ? Blo : Bhi;
#pragma unroll
            for (int ks = 0; ks < 4; ++ks) {
                wmma::fragment<wmma::matrix_b, 16, 16, 16, __nv_bfloat16, wmma::col_major> bf;
                wmma::load_matrix_sync(bf, Bp + wid * 16 * 64 + ks * 16, 64);
#pragma unroll
                for (int mt = 0; mt < 4; ++mt) {
                    wmma::fragment<wmma::matrix_a, 16, 16, 16, __nv_bfloat16, wmma::col_major> af;
                    wmma::load_matrix_sync(af, Ap + ks * 16 * 64 + mt * 16, 64);
                    wmma::mma_sync(acc[mt], af, bf, acc[mt]);
                }
            }
        }
    }
#pragma unroll
    for (int mt = 0; mt < 4; ++mt)
        wmma::store_matrix_sync(C + wid * 16 * 64 + mt * 16, acc[mt], 64, wmma::mem_col_major);
    __syncthreads();

    // ---- attn = v + t2/256; rewrite A (split) ----
    {
        const int p = tid & 63, jh = (tid >> 6) << 5;
        const int n = n0 + p;
        for (int i = 0; i < 32; ++i) {
            int j = jh + i;
            float at = fmaf(C[j * 64 + p], 1.f / 256.f, g_v[base + ((size_t)j << 16) + n]);
            __nv_bfloat16 h = __float2bfloat16(at);
            Ah[j * 64 + p] = h;
            Al[j * 64 + p] = __float2bfloat16(at - __bfloat162float(h));
        }
    }
    __syncthreads();

    // ---- MMA2: B = wln ----
#pragma unroll
    for (int mt = 0; mt < 4; ++mt) wmma::fill_fragment(acc[mt], 0.f);
#pragma unroll
    for (int term = 0; term < 3; ++term) {
        const __nv_bfloat16* Ap = (term == 2) ? Al : Ah;
        const __nv_bfloat16* Bp = (term == 1) ? g_wllo : g_wlhi;
#pragma unroll
        for (int ks = 0; ks < 4; ++ks) {
            wmma::fragment<wmma::matrix_b, 16, 16, 16, __nv_bfloat16, wmma::col_major> bf;
            wmma::load_matrix_sync(bf, Bp + wid * 16 * 64 + ks * 16, 64);
#pragma unroll
            for (int mt = 0; mt < 4; ++mt) {
                wmma::fragment<wmma::matrix_a, 16, 16, 16, __nv_bfloat16, wmma::col_major> af;
                wmma::load_matrix_sync(af, Ap + ks * 16 * 64 + mt * 16, 64);
                wmma::mma_sync(acc[mt], af, bf, acc[mt]);
            }
        }
    }
    __syncthreads();   // A reads done (A not reused, but C rewrite ordering is free)
#pragma unroll
    for (int mt = 0; mt < 4; ++mt)
        wmma::store_matrix_sync(C + wid * 16 * 64 + mt * 16, acc[mt], 64, wmma::mem_col_major);
    __syncthreads();

    // ---- out = C + bias ----
    {
        const int p = tid & 63, jh = (tid >> 6) << 5;
        const int n = n0 + p;
#pragma unroll 8
        for (int i = 0; i < 32; ++i) {
            int j = jh + i;
            out[base + ((size_t)j << 16) + n] = C[j * 64 + p] + bln[j];
        }
    }
}

// ---------------------------------------------------------------------------
extern "C" void kernel_launch(void* const* d_in, const int* in_sizes, int n_in,
                              void* d_out, int out_size) {
    const float* x    = (const float*)d_in[0];
    const float* wqkv = (const float*)d_in[1];
    const float* bqkv = (const float*)d_in[2];
    const float* wln  = (const float*)d_in[3];
    const float* bln  = (const float*)d_in[4];
    float* out = (float*)d_out;

    essa_prep<<<128, 256>>>(wqkv, wln);

    dim3 gridT(NPIX / 64, NBAT);
    essa_qkv_tc<<<gridT, 128>>>(x, bqkv);

    dim3 gridM(NPIX / 512, NBAT);
    essa_kvacc<<<gridM, 256>>>();

    essa_kvfin<<<128, 256>>>();

    essa_out_tc<<<gridT, 128>>>(bln, out);
}